// round 7
// baseline (speedup 1.0000x reference)
#include <cuda_runtime.h>
#include <math.h>

#define NAn 40000
#define NBn 40000
#define Hh  8
#define Cc  32
#define Dd  256
#define Ee  400000
#define BM  64
#define BK  32

// ---------------- device scratch (module globals; no runtime allocation) ----
__device__ __align__(256) float g_hA[(size_t)NAn * Dd];
__device__ __align__(256) float g_hB[(size_t)NBn * Dd];
__device__ __align__(256) float g_rel_ba[(size_t)NAn * Dd];
__device__ __align__(256) float g_rel_aa[(size_t)NAn * Dd];
__device__ __align__(256) float g_rel_ab[(size_t)NBn * Dd];
__device__ __align__(256) float g_al0[NAn * Hh];   // h_A . attn_l[0]
__device__ __align__(256) float g_ar1[NAn * Hh];   // h_A . attn_r[1]
__device__ __align__(256) float g_al2[NAn * Hh];   // h_A . attn_l[2]
__device__ __align__(256) float g_ar2[NAn * Hh];   // h_A . attn_r[2]
__device__ __align__(256) float g_ar0[NBn * Hh];   // h_B . attn_r[0]
__device__ __align__(256) float g_al1[NBn * Hh];   // h_B . attn_l[1]
__device__ __align__(256) float g_d_ba[NAn * Hh];
__device__ __align__(256) float g_d_aa[NAn * Hh];
__device__ __align__(256) float g_d_ab[NBn * Hh];

// ---------------- helpers ---------------------------------------------------
__device__ __forceinline__ float leaky(float x) { return x >= 0.f ? x : 0.2f * x; }
__device__ __forceinline__ float dot4(float4 a, float4 b) {
    return a.x * b.x + a.y * b.y + a.z * b.z + a.w * b.w;
}
__device__ __forceinline__ void red_add4(float* p, float a, float b, float c, float d) {
    asm volatile("red.global.add.v4.f32 [%0], {%1, %2, %3, %4};"
                 :: "l"(p), "f"(a), "f"(b), "f"(c), "f"(d)
                 : "memory");
}
__device__ __forceinline__ float wred8(float v) {
    v += __shfl_xor_sync(0xffffffffu, v, 1);
    v += __shfl_xor_sync(0xffffffffu, v, 2);
    v += __shfl_xor_sync(0xffffffffu, v, 4);
    return v;
}

// ---------------- fused GEMM: H = X@W + b, + alphas, + zero accumulators ----
// Tile 64 rows x 256 cols (full width). 256 threads: warp ty=tid>>5 owns rows
// ty*8..+7; lane tx owns cols {tx*4..+3, 128+tx*4..+3}. acc[8][2] float4.
// Epilogue: bias add, store H, zero rel/denom rows this block owns, and
// compute the per-(node,head) attention scalars from registers.
template <int MODE>  // 0 = A, 1 = B
__global__ void __launch_bounds__(256) k_gemm_fused(
    const float* __restrict__ X, const float* __restrict__ W,
    const float* __restrict__ bias,
    const float* __restrict__ attn_l, const float* __restrict__ attn_r) {
    __shared__ float As[BM][BK];     // 8 KB
    __shared__ float Bs[BK][256];    // 32 KB (reused for attn vectors later)

    const int tid = threadIdx.x;
    const int ty = tid >> 5;
    const int tx = tid & 31;
    const int bm = blockIdx.x * BM;

    float4 acc[8][2];
#pragma unroll
    for (int i = 0; i < 8; i++) {
        acc[i][0] = make_float4(0.f, 0.f, 0.f, 0.f);
        acc[i][1] = make_float4(0.f, 0.f, 0.f, 0.f);
    }

    const int lrow = tid >> 3;            // 0..31
    const int lkc = (tid & 7) * 4;        // 0..28

    for (int k0 = 0; k0 < Dd; k0 += BK) {
        // As: 64x32 (row-major like X). 2 float4 per thread, coalesced.
#pragma unroll
        for (int q = 0; q < 2; q++) {
            int row = lrow + q * 32;
            *(float4*)&As[row][lkc] =
                *(const float4*)&X[(size_t)(bm + row) * Dd + k0 + lkc];
        }
        // Bs: 32x256. 8 float4 per thread, coalesced, conflict-free STS.
#pragma unroll
        for (int q = 0; q < 8; q++) {
            int t4 = tid + 256 * q;
            int row = t4 >> 6;
            int c4 = (t4 & 63) * 4;
            *(float4*)&Bs[row][c4] =
                *(const float4*)&W[(size_t)(k0 + row) * Dd + c4];
        }
        __syncthreads();
#pragma unroll
        for (int k4 = 0; k4 < BK / 4; k4++) {
            float4 a4[8];
#pragma unroll
            for (int i = 0; i < 8; i++)
                a4[i] = *(float4*)&As[ty * 8 + i][k4 * 4];
#pragma unroll
            for (int kk = 0; kk < 4; kk++) {
                float4 b0 = *(float4*)&Bs[k4 * 4 + kk][tx * 4];
                float4 b1 = *(float4*)&Bs[k4 * 4 + kk][tx * 4 + 128];
#pragma unroll
                for (int i = 0; i < 8; i++) {
                    float a = (kk == 0) ? a4[i].x : (kk == 1) ? a4[i].y
                              : (kk == 2) ? a4[i].z : a4[i].w;
                    acc[i][0].x += a * b0.x; acc[i][0].y += a * b0.y;
                    acc[i][0].z += a * b0.z; acc[i][0].w += a * b0.w;
                    acc[i][1].x += a * b1.x; acc[i][1].y += a * b1.y;
                    acc[i][1].z += a * b1.z; acc[i][1].w += a * b1.w;
                }
            }
        }
        __syncthreads();
    }

    // ---- epilogue: bias, store H, zero rel rows --------------------------
    float* Hout = MODE ? g_hB : g_hA;
    float* rel0 = MODE ? g_rel_ab : g_rel_ba;

    float4 bb0 = *(const float4*)&bias[tx * 4];
    float4 bb1 = *(const float4*)&bias[tx * 4 + 128];
    const float4 z4 = make_float4(0.f, 0.f, 0.f, 0.f);

#pragma unroll
    for (int i = 0; i < 8; i++) {
        size_t base = (size_t)(bm + ty * 8 + i) * Dd;
        acc[i][0].x += bb0.x; acc[i][0].y += bb0.y;
        acc[i][0].z += bb0.z; acc[i][0].w += bb0.w;
        acc[i][1].x += bb1.x; acc[i][1].y += bb1.y;
        acc[i][1].z += bb1.z; acc[i][1].w += bb1.w;
        *(float4*)&Hout[base + tx * 4] = acc[i][0];
        *(float4*)&Hout[base + tx * 4 + 128] = acc[i][1];
        *(float4*)&rel0[base + tx * 4] = z4;
        *(float4*)&rel0[base + tx * 4 + 128] = z4;
        if (MODE == 0) {
            *(float4*)&g_rel_aa[base + tx * 4] = z4;
            *(float4*)&g_rel_aa[base + tx * 4 + 128] = z4;
        }
    }

    // ---- attn vectors into smem (reuse Bs) -------------------------------
    __syncthreads();
    float* sAttn = &Bs[0][0];
    if (MODE == 0) {
        sAttn[tid] = attn_l[tid];              // al0
        sAttn[256 + tid] = attn_r[256 + tid];  // ar1
        sAttn[512 + tid] = attn_l[512 + tid];  // al2
        sAttn[768 + tid] = attn_r[512 + tid];  // ar2
    } else {
        sAttn[tid] = attn_r[tid];              // ar0
        sAttn[256 + tid] = attn_l[256 + tid];  // al1
    }
    __syncthreads();

    // ---- alpha dots: col index == flat attn index ------------------------
    // head = c*4 + (tx>>3); sum over the 8 lanes varying (tx&7).
    float* aouts[4];
    if (MODE == 0) {
        aouts[0] = g_al0; aouts[1] = g_ar1; aouts[2] = g_al2; aouts[3] = g_ar2;
    } else {
        aouts[0] = g_ar0; aouts[1] = g_al1; aouts[2] = g_ar0; aouts[3] = g_al1;
    }
    const int NT = MODE ? 2 : 4;
    const bool writer = (tx & 7) == 0;
    const int hq = tx >> 3;  // head quadrant 0..3

#pragma unroll
    for (int t = 0; t < 4; t++) {
        if (t >= NT) break;
        float4 av0 = *(float4*)&sAttn[t * 256 + tx * 4];
        float4 av1 = *(float4*)&sAttn[t * 256 + tx * 4 + 128];
#pragma unroll
        for (int i = 0; i < 8; i++) {
            float d0 = wred8(dot4(acc[i][0], av0));
            float d1 = wred8(dot4(acc[i][1], av1));
            if (writer) {
                int row = bm + ty * 8 + i;
                aouts[t][row * Hh + hq] = d0;
                aouts[t][row * Hh + 4 + hq] = d1;
            }
        }
    }

    // ---- zero denominators ----------------------------------------------
    if (writer) {
#pragma unroll
        for (int i = 0; i < 8; i++) {
            int row = bm + ty * 8 + i;
            if (MODE == 0) {
                g_d_ba[row * Hh + hq] = 0.f; g_d_ba[row * Hh + 4 + hq] = 0.f;
                g_d_aa[row * Hh + hq] = 0.f; g_d_aa[row * Hh + 4 + hq] = 0.f;
            } else {
                g_d_ab[row * Hh + hq] = 0.f; g_d_ab[row * Hh + 4 + hq] = 0.f;
            }
        }
    }
}

// ---------------- edge aggregation (warp per edge, all 3 relations) ---------
// Lanes 0-7 compute the 8 per-head exponentials once (coalesced alpha loads,
// one denom atomic each); broadcast via shfl. h_src reads are two fully
// coalesced 128B float4 instructions.
__global__ void __launch_bounds__(256) k_edge_all(const int* __restrict__ e_ba,
                                                  const int* __restrict__ e_aa,
                                                  const int* __restrict__ e_ab) {
    int gw = (blockIdx.x * 256 + threadIdx.x) >> 5;
    const int lane = threadIdx.x & 31;
    const int* edge; const float *al, *ar, *Hs; float *rel, *den;
    if (gw < Ee) {
        edge = e_ba; al = g_al1; ar = g_ar1; Hs = g_hB; rel = g_rel_ba; den = g_d_ba;
    } else if (gw < 2 * Ee) {
        gw -= Ee;
        edge = e_aa; al = g_al2; ar = g_ar2; Hs = g_hA; rel = g_rel_aa; den = g_d_aa;
    } else if (gw < 3 * Ee) {
        gw -= 2 * Ee;
        edge = e_ab; al = g_al0; ar = g_ar0; Hs = g_hA; rel = g_rel_ab; den = g_d_ab;
    } else {
        return;
    }

    int s = __ldg(&edge[gw]);
    int d = __ldg(&edge[Ee + gw]);

    float exv = 0.f;
    if (lane < Hh) {
        float e = __ldg(&al[s * Hh + lane]) + __ldg(&ar[d * Hh + lane]);
        exv = __expf(leaky(e));
        atomicAdd(&den[d * Hh + lane], exv);
    }
    float ex0 = __shfl_sync(0xffffffffu, exv, lane >> 3);        // head 0..3
    float ex1 = __shfl_sync(0xffffffffu, exv, 4 + (lane >> 3));  // head 4..7

    const float4* hp = (const float4*)(Hs + (size_t)s * Dd);
    float4 v0 = __ldg(hp + lane);        // cols lane*4       (head lane>>3)
    float4 v1 = __ldg(hp + 32 + lane);   // cols 128+lane*4   (head 4+(lane>>3))
    float* rp = rel + (size_t)d * Dd;
    red_add4(rp + lane * 4,       v0.x * ex0, v0.y * ex0, v0.z * ex0, v0.w * ex0);
    red_add4(rp + 128 + lane * 4, v1.x * ex1, v1.y * ex1, v1.z * ex1, v1.w * ex1);
}

// ---------------- finalize: normalize + beta combine + relu -----------------
#define QR(v) v += __shfl_xor_sync(0xffffffffu, v, 1); v += __shfl_xor_sync(0xffffffffu, v, 2);

__global__ void __launch_bounds__(256) k_final_A(const float* __restrict__ rel_l,
                                                 const float* __restrict__ rel_r,
                                                 float* __restrict__ out) {
    int gw = (blockIdx.x * 256 + threadIdx.x) >> 5;
    if (gw >= NAn) return;
    int lane = threadIdx.x & 31;
    int n = gw;
    int off = lane * 8;       // == h*32 + (lane&3)*8
    int h = lane >> 2;
    size_t base = (size_t)n * Dd + off;

    float4 h0 = *(const float4*)(g_hA + base);
    float4 h1 = *(const float4*)(g_hA + base + 4);
    float dba = g_d_ba[n * Hh + h];
    float daa = g_d_aa[n * Hh + h];
    float i0 = dba > 0.f ? 1.f / dba : 0.f;
    float i1 = daa > 0.f ? 1.f / daa : 0.f;
    float4 e00 = *(const float4*)(g_rel_ba + base);
    float4 e01 = *(const float4*)(g_rel_ba + base + 4);
    float4 e10 = *(const float4*)(g_rel_aa + base);
    float4 e11 = *(const float4*)(g_rel_aa + base + 4);
    e00.x *= i0; e00.y *= i0; e00.z *= i0; e00.w *= i0;
    e01.x *= i0; e01.y *= i0; e01.z *= i0; e01.w *= i0;
    e10.x *= i1; e10.y *= i1; e10.z *= i1; e10.w *= i1;
    e11.x *= i1; e11.y *= i1; e11.z *= i1; e11.w *= i1;

    float4 rl0 = *(const float4*)(rel_l + off);
    float4 rl1 = *(const float4*)(rel_l + off + 4);
    float4 rr0 = *(const float4*)(rel_r + off);
    float4 rr1 = *(const float4*)(rel_r + off + 4);

    float bl = dot4(h0, rl0) + dot4(h1, rl1);
    float b0 = dot4(e00, rr0) + dot4(e01, rr1);
    float b1 = dot4(e10, rr0) + dot4(e11, rr1);
    float b2 = dot4(h0, rr0) + dot4(h1, rr1);
    QR(bl) QR(b0) QR(b1) QR(b2)

    float s0 = leaky(bl + b0), s1 = leaky(bl + b1), s2 = leaky(bl + b2);
    float mx = fmaxf(s0, fmaxf(s1, s2));
    float w0 = __expf(s0 - mx), w1 = __expf(s1 - mx), w2 = __expf(s2 - mx);
    float inv = 1.f / (w0 + w1 + w2);
    w0 *= inv; w1 *= inv; w2 *= inv;

    float4 o0, o1;
    o0.x = fmaxf(e00.x * w0 + e10.x * w1 + h0.x * w2, 0.f);
    o0.y = fmaxf(e00.y * w0 + e10.y * w1 + h0.y * w2, 0.f);
    o0.z = fmaxf(e00.z * w0 + e10.z * w1 + h0.z * w2, 0.f);
    o0.w = fmaxf(e00.w * w0 + e10.w * w1 + h0.w * w2, 0.f);
    o1.x = fmaxf(e01.x * w0 + e11.x * w1 + h1.x * w2, 0.f);
    o1.y = fmaxf(e01.y * w0 + e11.y * w1 + h1.y * w2, 0.f);
    o1.z = fmaxf(e01.z * w0 + e11.z * w1 + h1.z * w2, 0.f);
    o1.w = fmaxf(e01.w * w0 + e11.w * w1 + h1.w * w2, 0.f);
    *(float4*)(out + base) = o0;
    *(float4*)(out + base + 4) = o1;
}

__global__ void __launch_bounds__(256) k_final_B(const float* __restrict__ rel_l,
                                                 const float* __restrict__ rel_r,
                                                 float* __restrict__ out) {
    int gw = (blockIdx.x * 256 + threadIdx.x) >> 5;
    if (gw >= NBn) return;
    int lane = threadIdx.x & 31;
    int n = gw;
    int off = lane * 8;
    int h = lane >> 2;
    size_t base = (size_t)n * Dd + off;

    float4 h0 = *(const float4*)(g_hB + base);
    float4 h1 = *(const float4*)(g_hB + base + 4);
    float dab = g_d_ab[n * Hh + h];
    float i0 = dab > 0.f ? 1.f / dab : 0.f;
    float4 e00 = *(const float4*)(g_rel_ab + base);
    float4 e01 = *(const float4*)(g_rel_ab + base + 4);
    e00.x *= i0; e00.y *= i0; e00.z *= i0; e00.w *= i0;
    e01.x *= i0; e01.y *= i0; e01.z *= i0; e01.w *= i0;

    float4 rl0 = *(const float4*)(rel_l + off);
    float4 rl1 = *(const float4*)(rel_l + off + 4);
    float4 rr0 = *(const float4*)(rel_r + off);
    float4 rr1 = *(const float4*)(rel_r + off + 4);

    float bl = dot4(h0, rl0) + dot4(h1, rl1);
    float b0 = dot4(e00, rr0) + dot4(e01, rr1);
    float b1 = dot4(h0, rr0) + dot4(h1, rr1);
    QR(bl) QR(b0) QR(b1)

    float s0 = leaky(bl + b0), s1 = leaky(bl + b1);
    float mx = fmaxf(s0, s1);
    float w0 = __expf(s0 - mx), w1 = __expf(s1 - mx);
    float inv = 1.f / (w0 + w1);
    w0 *= inv; w1 *= inv;

    float4 o0, o1;
    o0.x = fmaxf(e00.x * w0 + h0.x * w1, 0.f);
    o0.y = fmaxf(e00.y * w0 + h0.y * w1, 0.f);
    o0.z = fmaxf(e00.z * w0 + h0.z * w1, 0.f);
    o0.w = fmaxf(e00.w * w0 + h0.w * w1, 0.f);
    o1.x = fmaxf(e01.x * w0 + h1.x * w1, 0.f);
    o1.y = fmaxf(e01.y * w0 + h1.y * w1, 0.f);
    o1.z = fmaxf(e01.z * w0 + h1.z * w1, 0.f);
    o1.w = fmaxf(e01.w * w0 + h1.w * w1, 0.f);
    size_t obase = (size_t)(NAn + n) * Dd + off;
    *(float4*)(out + obase) = o0;
    *(float4*)(out + obase + 4) = o1;
}

// ---------------- launch -----------------------------------------------------
extern "C" void kernel_launch(void* const* d_in, const int* in_sizes, int n_in,
                              void* d_out, int out_size) {
    const float* xA     = (const float*)d_in[0];
    const float* xB     = (const float*)d_in[1];
    const int*   e_ab   = (const int*)d_in[2];
    const int*   e_ba   = (const int*)d_in[3];
    const int*   e_aa   = (const int*)d_in[4];
    const float* WA     = (const float*)d_in[5];
    const float* bA     = (const float*)d_in[6];
    const float* WB     = (const float*)d_in[7];
    const float* bB     = (const float*)d_in[8];
    const float* attn_l = (const float*)d_in[9];
    const float* attn_r = (const float*)d_in[10];
    const float* rlA    = (const float*)d_in[11];
    const float* rrA    = (const float*)d_in[12];
    const float* rlB    = (const float*)d_in[13];
    const float* rrB    = (const float*)d_in[14];
    float* out = (float*)d_out;

    k_gemm_fused<0><<<NAn / BM, 256>>>(xA, WA, bA, attn_l, attn_r);
    k_gemm_fused<1><<<NBn / BM, 256>>>(xB, WB, bB, attn_l, attn_r);
    k_edge_all<<<(3 * Ee * 32 + 255) / 256, 256>>>(e_ba, e_aa, e_ab);
    k_final_A<<<(NAn * 32 + 255) / 256, 256>>>(rlA, rrA, out);
    k_final_B<<<(NBn * 32 + 255) / 256, 256>>>(rlB, rrB, out);
}

// round 8
// speedup vs baseline: 1.6961x; 1.6961x over previous
#include <cuda_runtime.h>
#include <math.h>

#define NAn 40000
#define NBn 40000
#define Hh  8
#define Cc  32
#define Dd  256
#define Ee  400000

// ---------------- device scratch (module globals; no runtime allocation) ----
__device__ __align__(256) float g_hA[(size_t)NAn * Dd];
__device__ __align__(256) float g_hB[(size_t)NBn * Dd];
__device__ __align__(256) float g_rel_ba[(size_t)NAn * Dd];
__device__ __align__(256) float g_rel_aa[(size_t)NAn * Dd];
__device__ __align__(256) float g_rel_ab[(size_t)NBn * Dd];
__device__ __align__(256) float g_al0[NAn * Hh];
__device__ __align__(256) float g_ar1[NAn * Hh];
__device__ __align__(256) float g_al2[NAn * Hh];
__device__ __align__(256) float g_ar2[NAn * Hh];
__device__ __align__(256) float g_ar0[NBn * Hh];
__device__ __align__(256) float g_al1[NBn * Hh];
__device__ __align__(256) float g_d_ba[NAn * Hh];
__device__ __align__(256) float g_d_aa[NAn * Hh];
__device__ __align__(256) float g_d_ab[NBn * Hh];

// ---------------- helpers ---------------------------------------------------
__device__ __forceinline__ float leaky(float x) { return x >= 0.f ? x : 0.2f * x; }
__device__ __forceinline__ float dot4(float4 a, float4 b) {
    return a.x * b.x + a.y * b.y + a.z * b.z + a.w * b.w;
}
__device__ __forceinline__ void red_add4(float* p, float a, float b, float c, float d) {
    asm volatile("red.global.add.v4.f32 [%0], {%1, %2, %3, %4};"
                 :: "l"(p), "f"(a), "f"(b), "f"(c), "f"(d)
                 : "memory");
}

// ---------------- GEMM: H = X@W + b (M x 256 x 256), 128x128x16, 8x8/thread -
// Epilogue also zeroes the rel accumulator patch this block owns (kills k_init).
template <int MODE>  // 0 = A, 1 = B
__global__ void __launch_bounds__(256, 2) k_gemm(const float* __restrict__ X,
                                                 const float* __restrict__ W,
                                                 const float* __restrict__ bias) {
    __shared__ float As[16][128];
    __shared__ float Bs[16][128];
    const int tid = threadIdx.x;
    const int bn = blockIdx.x * 128;
    const int bm = blockIdx.y * 128;
    const int M = MODE ? NBn : NAn;
    const int tx8 = tid & 15;
    const int ty8 = tid >> 4;

    float acc[8][8];
#pragma unroll
    for (int i = 0; i < 8; i++)
#pragma unroll
        for (int j = 0; j < 8; j++) acc[i][j] = 0.f;

    const int arow = tid >> 1;         // 0..127
    const int akc = (tid & 1) * 8;     // 0 or 8
    const int brow = tid >> 4;         // 0..15
    const int bcol = (tid & 15) * 4;   // 0..60

    const int gr = min(bm + arow, M - 1);  // clamped load row (tail-safe)

    for (int k0 = 0; k0 < Dd; k0 += 16) {
        float4 a0 = *(const float4*)&X[(size_t)gr * Dd + k0 + akc];
        float4 a1 = *(const float4*)&X[(size_t)gr * Dd + k0 + akc + 4];
        As[akc + 0][arow] = a0.x; As[akc + 1][arow] = a0.y;
        As[akc + 2][arow] = a0.z; As[akc + 3][arow] = a0.w;
        As[akc + 4][arow] = a1.x; As[akc + 5][arow] = a1.y;
        As[akc + 6][arow] = a1.z; As[akc + 7][arow] = a1.w;
        *(float4*)&Bs[brow][bcol] =
            *(const float4*)&W[(size_t)(k0 + brow) * Dd + bn + bcol];
        *(float4*)&Bs[brow][bcol + 64] =
            *(const float4*)&W[(size_t)(k0 + brow) * Dd + bn + bcol + 64];
        __syncthreads();
#pragma unroll
        for (int k = 0; k < 16; k++) {
            float a[8], b[8];
            *(float4*)&a[0] = *(float4*)&As[k][ty8 * 4];
            *(float4*)&a[4] = *(float4*)&As[k][64 + ty8 * 4];
            *(float4*)&b[0] = *(float4*)&Bs[k][tx8 * 4];
            *(float4*)&b[4] = *(float4*)&Bs[k][64 + tx8 * 4];
#pragma unroll
            for (int i = 0; i < 8; i++)
#pragma unroll
                for (int j = 0; j < 8; j++) acc[i][j] += a[i] * b[j];
        }
        __syncthreads();
    }

    float* Hout = MODE ? g_hB : g_hA;
    float* rel0 = MODE ? g_rel_ab : g_rel_ba;
    float4 bb0 = *(const float4*)&bias[bn + tx8 * 4];
    float4 bb1 = *(const float4*)&bias[bn + 64 + tx8 * 4];
    const float4 z4 = make_float4(0.f, 0.f, 0.f, 0.f);

#pragma unroll
    for (int i = 0; i < 8; i++) {
        int row = bm + ((i < 4) ? (ty8 * 4 + i) : (64 + ty8 * 4 + i - 4));
        if (row >= M) continue;
        size_t base = (size_t)row * Dd + bn;
        float4 o0 = make_float4(acc[i][0] + bb0.x, acc[i][1] + bb0.y,
                                acc[i][2] + bb0.z, acc[i][3] + bb0.w);
        float4 o1 = make_float4(acc[i][4] + bb1.x, acc[i][5] + bb1.y,
                                acc[i][6] + bb1.z, acc[i][7] + bb1.w);
        *(float4*)&Hout[base + tx8 * 4] = o0;
        *(float4*)&Hout[base + tx8 * 4 + 64] = o1;
        *(float4*)&rel0[base + tx8 * 4] = z4;
        *(float4*)&rel0[base + tx8 * 4 + 64] = z4;
        if (MODE == 0) {
            *(float4*)&g_rel_aa[base + tx8 * 4] = z4;
            *(float4*)&g_rel_aa[base + tx8 * 4 + 64] = z4;
        }
    }
}

// ---------------- alphas: warp per node, coalesced; also zero denominators --
__global__ void __launch_bounds__(256) k_alpha(const float* __restrict__ attn_l,
                                               const float* __restrict__ attn_r) {
    int gw = (blockIdx.x * 256 + threadIdx.x) >> 5;
    const int lane = threadIdx.x & 31;
    const int off = lane * 8;      // = h*32 + (lane&3)*8
    const int h = lane >> 2;
    const bool wr = (lane & 3) == 0;

    if (gw < NAn) {
        int n = gw;
        size_t base = (size_t)n * Dd + off;
        float4 v0 = *(const float4*)(g_hA + base);
        float4 v1 = *(const float4*)(g_hA + base + 4);
        float d0 = dot4(v0, __ldg((const float4*)(attn_l + off)))
                 + dot4(v1, __ldg((const float4*)(attn_l + off + 4)));
        float d1 = dot4(v0, __ldg((const float4*)(attn_r + 256 + off)))
                 + dot4(v1, __ldg((const float4*)(attn_r + 256 + off + 4)));
        float d2 = dot4(v0, __ldg((const float4*)(attn_l + 512 + off)))
                 + dot4(v1, __ldg((const float4*)(attn_l + 512 + off + 4)));
        float d3 = dot4(v0, __ldg((const float4*)(attn_r + 512 + off)))
                 + dot4(v1, __ldg((const float4*)(attn_r + 512 + off + 4)));
#define R2(v) v += __shfl_xor_sync(0xffffffffu, v, 1); v += __shfl_xor_sync(0xffffffffu, v, 2);
        R2(d0) R2(d1) R2(d2) R2(d3)
        if (wr) {
            g_al0[n * Hh + h] = d0;
            g_ar1[n * Hh + h] = d1;
            g_al2[n * Hh + h] = d2;
            g_ar2[n * Hh + h] = d3;
            g_d_ba[n * Hh + h] = 0.f;
            g_d_aa[n * Hh + h] = 0.f;
        }
    } else if (gw < NAn + NBn) {
        int n = gw - NAn;
        size_t base = (size_t)n * Dd + off;
        float4 v0 = *(const float4*)(g_hB + base);
        float4 v1 = *(const float4*)(g_hB + base + 4);
        float d0 = dot4(v0, __ldg((const float4*)(attn_r + off)))
                 + dot4(v1, __ldg((const float4*)(attn_r + off + 4)));
        float d1 = dot4(v0, __ldg((const float4*)(attn_l + 256 + off)))
                 + dot4(v1, __ldg((const float4*)(attn_l + 256 + off + 4)));
        R2(d0) R2(d1)
        if (wr) {
            g_ar0[n * Hh + h] = d0;
            g_al1[n * Hh + h] = d1;
            g_d_ab[n * Hh + h] = 0.f;
        }
    }
}

// ---------------- edge aggregation (warp per edge; one relation per launch) -
// Lanes 0-7 compute the 8 per-head exponentials (coalesced alpha loads, one
// denom atomic each); broadcast via shfl. h_src reads: 2 coalesced 128B insts.
template <int RID>  // 0 = ba (B->A), 1 = aa, 2 = ab (A->B)
__global__ void __launch_bounds__(256) k_edge(const int* __restrict__ edge) {
    const float* al = (RID == 0) ? g_al1 : (RID == 1) ? g_al2 : g_al0;
    const float* ar = (RID == 0) ? g_ar1 : (RID == 1) ? g_ar2 : g_ar0;
    const float* Hs = (RID == 0) ? g_hB : g_hA;
    float* rel = (RID == 0) ? g_rel_ba : (RID == 1) ? g_rel_aa : g_rel_ab;
    float* den = (RID == 0) ? g_d_ba : (RID == 1) ? g_d_aa : g_d_ab;

    int gw = (blockIdx.x * 256 + threadIdx.x) >> 5;
    if (gw >= Ee) return;
    const int lane = threadIdx.x & 31;

    int s = __ldg(&edge[gw]);
    int d = __ldg(&edge[Ee + gw]);

    float exv = 0.f;
    if (lane < Hh) {
        float e = __ldg(&al[s * Hh + lane]) + __ldg(&ar[d * Hh + lane]);
        exv = __expf(leaky(e));
        atomicAdd(&den[d * Hh + lane], exv);
    }
    float ex0 = __shfl_sync(0xffffffffu, exv, lane >> 3);        // heads 0..3
    float ex1 = __shfl_sync(0xffffffffu, exv, 4 + (lane >> 3));  // heads 4..7

    const float4* hp = (const float4*)(Hs + (size_t)s * Dd);
    float4 v0 = __ldg(hp + lane);
    float4 v1 = __ldg(hp + 32 + lane);
    float* rp = rel + (size_t)d * Dd;
    red_add4(rp + lane * 4,       v0.x * ex0, v0.y * ex0, v0.z * ex0, v0.w * ex0);
    red_add4(rp + 128 + lane * 4, v1.x * ex1, v1.y * ex1, v1.z * ex1, v1.w * ex1);
}

// ---------------- finalize (merged A+B): normalize + beta combine + relu ----
#define QR(v) v += __shfl_xor_sync(0xffffffffu, v, 1); v += __shfl_xor_sync(0xffffffffu, v, 2);

__global__ void __launch_bounds__(256) k_final(const float* __restrict__ rlA,
                                               const float* __restrict__ rrA,
                                               const float* __restrict__ rlB,
                                               const float* __restrict__ rrB,
                                               float* __restrict__ out) {
    int gw = (blockIdx.x * 256 + threadIdx.x) >> 5;
    const int lane = threadIdx.x & 31;
    const int off = lane * 8;
    const int h = lane >> 2;

    if (gw < NAn) {
        int n = gw;
        size_t base = (size_t)n * Dd + off;
        float4 h0 = *(const float4*)(g_hA + base);
        float4 h1 = *(const float4*)(g_hA + base + 4);
        float dba = g_d_ba[n * Hh + h];
        float daa = g_d_aa[n * Hh + h];
        float i0 = dba > 0.f ? 1.f / dba : 0.f;
        float i1 = daa > 0.f ? 1.f / daa : 0.f;
        float4 e00 = *(const float4*)(g_rel_ba + base);
        float4 e01 = *(const float4*)(g_rel_ba + base + 4);
        float4 e10 = *(const float4*)(g_rel_aa + base);
        float4 e11 = *(const float4*)(g_rel_aa + base + 4);
        e00.x *= i0; e00.y *= i0; e00.z *= i0; e00.w *= i0;
        e01.x *= i0; e01.y *= i0; e01.z *= i0; e01.w *= i0;
        e10.x *= i1; e10.y *= i1; e10.z *= i1; e10.w *= i1;
        e11.x *= i1; e11.y *= i1; e11.z *= i1; e11.w *= i1;

        float4 rl0 = *(const float4*)(rlA + off);
        float4 rl1 = *(const float4*)(rlA + off + 4);
        float4 rr0 = *(const float4*)(rrA + off);
        float4 rr1 = *(const float4*)(rrA + off + 4);

        float bl = dot4(h0, rl0) + dot4(h1, rl1);
        float b0 = dot4(e00, rr0) + dot4(e01, rr1);
        float b1 = dot4(e10, rr0) + dot4(e11, rr1);
        float b2 = dot4(h0, rr0) + dot4(h1, rr1);
        QR(bl) QR(b0) QR(b1) QR(b2)

        float s0 = leaky(bl + b0), s1 = leaky(bl + b1), s2 = leaky(bl + b2);
        float mx = fmaxf(s0, fmaxf(s1, s2));
        float w0 = __expf(s0 - mx), w1 = __expf(s1 - mx), w2 = __expf(s2 - mx);
        float inv = 1.f / (w0 + w1 + w2);
        w0 *= inv; w1 *= inv; w2 *= inv;

        float4 o0, o1;
        o0.x = fmaxf(e00.x * w0 + e10.x * w1 + h0.x * w2, 0.f);
        o0.y = fmaxf(e00.y * w0 + e10.y * w1 + h0.y * w2, 0.f);
        o0.z = fmaxf(e00.z * w0 + e10.z * w1 + h0.z * w2, 0.f);
        o0.w = fmaxf(e00.w * w0 + e10.w * w1 + h0.w * w2, 0.f);
        o1.x = fmaxf(e01.x * w0 + e11.x * w1 + h1.x * w2, 0.f);
        o1.y = fmaxf(e01.y * w0 + e11.y * w1 + h1.y * w2, 0.f);
        o1.z = fmaxf(e01.z * w0 + e11.z * w1 + h1.z * w2, 0.f);
        o1.w = fmaxf(e01.w * w0 + e11.w * w1 + h1.w * w2, 0.f);
        *(float4*)(out + base) = o0;
        *(float4*)(out + base + 4) = o1;
    } else if (gw < NAn + NBn) {
        int n = gw - NAn;
        size_t base = (size_t)n * Dd + off;
        float4 h0 = *(const float4*)(g_hB + base);
        float4 h1 = *(const float4*)(g_hB + base + 4);
        float dab = g_d_ab[n * Hh + h];
        float i0 = dab > 0.f ? 1.f / dab : 0.f;
        float4 e00 = *(const float4*)(g_rel_ab + base);
        float4 e01 = *(const float4*)(g_rel_ab + base + 4);
        e00.x *= i0; e00.y *= i0; e00.z *= i0; e00.w *= i0;
        e01.x *= i0; e01.y *= i0; e01.z *= i0; e01.w *= i0;

        float4 rl0 = *(const float4*)(rlB + off);
        float4 rl1 = *(const float4*)(rlB + off + 4);
        float4 rr0 = *(const float4*)(rrB + off);
        float4 rr1 = *(const float4*)(rrB + off + 4);

        float bl = dot4(h0, rl0) + dot4(h1, rl1);
        float b0 = dot4(e00, rr0) + dot4(e01, rr1);
        float b1 = dot4(h0, rr0) + dot4(h1, rr1);
        QR(bl) QR(b0) QR(b1)

        float s0 = leaky(bl + b0), s1 = leaky(bl + b1);
        float mx = fmaxf(s0, s1);
        float w0 = __expf(s0 - mx), w1 = __expf(s1 - mx);
        float inv = 1.f / (w0 + w1);
        w0 *= inv; w1 *= inv;

        float4 o0, o1;
        o0.x = fmaxf(e00.x * w0 + h0.x * w1, 0.f);
        o0.y = fmaxf(e00.y * w0 + h0.y * w1, 0.f);
        o0.z = fmaxf(e00.z * w0 + h0.z * w1, 0.f);
        o0.w = fmaxf(e00.w * w0 + h0.w * w1, 0.f);
        o1.x = fmaxf(e01.x * w0 + h1.x * w1, 0.f);
        o1.y = fmaxf(e01.y * w0 + h1.y * w1, 0.f);
        o1.z = fmaxf(e01.z * w0 + h1.z * w1, 0.f);
        o1.w = fmaxf(e01.w * w0 + h1.w * w1, 0.f);
        size_t obase = (size_t)(NAn + n) * Dd + off;
        *(float4*)(out + obase) = o0;
        *(float4*)(out + obase + 4) = o1;
    }
}

// ---------------- launch -----------------------------------------------------
extern "C" void kernel_launch(void* const* d_in, const int* in_sizes, int n_in,
                              void* d_out, int out_size) {
    const float* xA     = (const float*)d_in[0];
    const float* xB     = (const float*)d_in[1];
    const int*   e_ab   = (const int*)d_in[2];
    const int*   e_ba   = (const int*)d_in[3];
    const int*   e_aa   = (const int*)d_in[4];
    const float* WA     = (const float*)d_in[5];
    const float* bA     = (const float*)d_in[6];
    const float* WB     = (const float*)d_in[7];
    const float* bB     = (const float*)d_in[8];
    const float* attn_l = (const float*)d_in[9];
    const float* attn_r = (const float*)d_in[10];
    const float* rlA    = (const float*)d_in[11];
    const float* rrA    = (const float*)d_in[12];
    const float* rlB    = (const float*)d_in[13];
    const float* rrB    = (const float*)d_in[14];
    float* out = (float*)d_out;

    dim3 gg(2, (NAn + 127) / 128);
    k_gemm<0><<<gg, 256>>>(xA, WA, bA);
    k_gemm<1><<<gg, 256>>>(xB, WB, bB);
    k_alpha<<<((NAn + NBn) * 32 + 255) / 256, 256>>>(attn_l, attn_r);
    k_edge<0><<<(Ee * 32 + 255) / 256, 256>>>(e_ba);
    k_edge<1><<<(Ee * 32 + 255) / 256, 256>>>(e_aa);
    k_edge<2><<<(Ee * 32 + 255) / 256, 256>>>(e_ab);
    k_final<<<((NAn + NBn) * 32 + 255) / 256, 256>>>(rlA, rrA, rlB, rrB, out);
}

// round 11
// speedup vs baseline: 1.8364x; 1.0827x over previous
#include <cuda_runtime.h>
#include <math.h>

#define NAn 40000
#define NBn 40000
#define Hh  8
#define Cc  32
#define Dd  256
#define Ee  400000

// ---------------- device scratch (module globals; no runtime allocation) ----
__device__ __align__(256) float g_hA[(size_t)NAn * Dd];
__device__ __align__(256) float g_hB[(size_t)NBn * Dd];
__device__ __align__(256) float g_rel_ba[(size_t)NAn * Dd];
__device__ __align__(256) float g_rel_aa[(size_t)NAn * Dd];
__device__ __align__(256) float g_rel_ab[(size_t)NBn * Dd];
__device__ __align__(256) float g_al0[NAn * Hh];
__device__ __align__(256) float g_ar1[NAn * Hh];
__device__ __align__(256) float g_al2[NAn * Hh];
__device__ __align__(256) float g_ar2[NAn * Hh];
__device__ __align__(256) float g_ar0[NBn * Hh];
__device__ __align__(256) float g_al1[NBn * Hh];
// CSR scratch (dst-bucketed adjacency, rebuilt every call)
__device__ int g_deg[3][NAn];
__device__ int g_off[3][NAn + 1];
__device__ int g_cur[3][NAn];
__device__ int g_perm[3][Ee];   // src node per CSR slot

// ---------------- helpers ---------------------------------------------------
__device__ __forceinline__ float leaky(float x) { return x >= 0.f ? x : 0.2f * x; }
__device__ __forceinline__ float dot4(float4 a, float4 b) {
    return a.x * b.x + a.y * b.y + a.z * b.z + a.w * b.w;
}

// ---------------- GEMM: H = X@W + b (M x 256 x 256), 128x128x16, 8x8/thread -
template <int MODE>  // 0 = A, 1 = B
__global__ void __launch_bounds__(256, 2) k_gemm(const float* __restrict__ X,
                                                 const float* __restrict__ W,
                                                 const float* __restrict__ bias) {
    __shared__ float As[16][128];
    __shared__ float Bs[16][128];
    const int tid = threadIdx.x;
    const int bn = blockIdx.x * 128;
    const int bm = blockIdx.y * 128;
    const int M = MODE ? NBn : NAn;
    const int tx8 = tid & 15;
    const int ty8 = tid >> 4;

    float acc[8][8];
#pragma unroll
    for (int i = 0; i < 8; i++)
#pragma unroll
        for (int j = 0; j < 8; j++) acc[i][j] = 0.f;

    const int arow = tid >> 1;
    const int akc = (tid & 1) * 8;
    const int brow = tid >> 4;
    const int bcol = (tid & 15) * 4;
    const int gr = min(bm + arow, M - 1);

    for (int k0 = 0; k0 < Dd; k0 += 16) {
        float4 a0 = *(const float4*)&X[(size_t)gr * Dd + k0 + akc];
        float4 a1 = *(const float4*)&X[(size_t)gr * Dd + k0 + akc + 4];
        As[akc + 0][arow] = a0.x; As[akc + 1][arow] = a0.y;
        As[akc + 2][arow] = a0.z; As[akc + 3][arow] = a0.w;
        As[akc + 4][arow] = a1.x; As[akc + 5][arow] = a1.y;
        As[akc + 6][arow] = a1.z; As[akc + 7][arow] = a1.w;
        *(float4*)&Bs[brow][bcol] =
            *(const float4*)&W[(size_t)(k0 + brow) * Dd + bn + bcol];
        *(float4*)&Bs[brow][bcol + 64] =
            *(const float4*)&W[(size_t)(k0 + brow) * Dd + bn + bcol + 64];
        __syncthreads();
#pragma unroll
        for (int k = 0; k < 16; k++) {
            float a[8], b[8];
            *(float4*)&a[0] = *(float4*)&As[k][ty8 * 4];
            *(float4*)&a[4] = *(float4*)&As[k][64 + ty8 * 4];
            *(float4*)&b[0] = *(float4*)&Bs[k][tx8 * 4];
            *(float4*)&b[4] = *(float4*)&Bs[k][64 + tx8 * 4];
#pragma unroll
            for (int i = 0; i < 8; i++)
#pragma unroll
                for (int j = 0; j < 8; j++) acc[i][j] += a[i] * b[j];
        }
        __syncthreads();
    }

    float* Hout = MODE ? g_hB : g_hA;
    float4 bb0 = *(const float4*)&bias[bn + tx8 * 4];
    float4 bb1 = *(const float4*)&bias[bn + 64 + tx8 * 4];

#pragma unroll
    for (int i = 0; i < 8; i++) {
        int row = bm + ((i < 4) ? (ty8 * 4 + i) : (64 + ty8 * 4 + i - 4));
        if (row >= M) continue;
        size_t base = (size_t)row * Dd + bn;
        float4 o0 = make_float4(acc[i][0] + bb0.x, acc[i][1] + bb0.y,
                                acc[i][2] + bb0.z, acc[i][3] + bb0.w);
        float4 o1 = make_float4(acc[i][4] + bb1.x, acc[i][5] + bb1.y,
                                acc[i][6] + bb1.z, acc[i][7] + bb1.w);
        *(float4*)&Hout[base + tx8 * 4] = o0;
        *(float4*)&Hout[base + tx8 * 4 + 64] = o1;
    }
}

// ---------------- alphas: warp per node, coalesced --------------------------
__global__ void __launch_bounds__(256) k_alpha(const float* __restrict__ attn_l,
                                               const float* __restrict__ attn_r) {
    int gw = (blockIdx.x * 256 + threadIdx.x) >> 5;
    const int lane = threadIdx.x & 31;
    const int off = lane * 8;
    const int h = lane >> 2;
    const bool wr = (lane & 3) == 0;
#define R2(v) v += __shfl_xor_sync(0xffffffffu, v, 1); v += __shfl_xor_sync(0xffffffffu, v, 2);

    if (gw < NAn) {
        int n = gw;
        size_t base = (size_t)n * Dd + off;
        float4 v0 = *(const float4*)(g_hA + base);
        float4 v1 = *(const float4*)(g_hA + base + 4);
        float d0 = dot4(v0, __ldg((const float4*)(attn_l + off)))
                 + dot4(v1, __ldg((const float4*)(attn_l + off + 4)));
        float d1 = dot4(v0, __ldg((const float4*)(attn_r + 256 + off)))
                 + dot4(v1, __ldg((const float4*)(attn_r + 256 + off + 4)));
        float d2 = dot4(v0, __ldg((const float4*)(attn_l + 512 + off)))
                 + dot4(v1, __ldg((const float4*)(attn_l + 512 + off + 4)));
        float d3 = dot4(v0, __ldg((const float4*)(attn_r + 512 + off)))
                 + dot4(v1, __ldg((const float4*)(attn_r + 512 + off + 4)));
        R2(d0) R2(d1) R2(d2) R2(d3)
        if (wr) {
            g_al0[n * Hh + h] = d0;
            g_ar1[n * Hh + h] = d1;
            g_al2[n * Hh + h] = d2;
            g_ar2[n * Hh + h] = d3;
        }
    } else if (gw < NAn + NBn) {
        int n = gw - NAn;
        size_t base = (size_t)n * Dd + off;
        float4 v0 = *(const float4*)(g_hB + base);
        float4 v1 = *(const float4*)(g_hB + base + 4);
        float d0 = dot4(v0, __ldg((const float4*)(attn_r + off)))
                 + dot4(v1, __ldg((const float4*)(attn_r + off + 4)));
        float d1 = dot4(v0, __ldg((const float4*)(attn_l + 256 + off)))
                 + dot4(v1, __ldg((const float4*)(attn_l + 256 + off + 4)));
        R2(d0) R2(d1)
        if (wr) {
            g_ar0[n * Hh + h] = d0;
            g_al1[n * Hh + h] = d1;
        }
    }
}

// ---------------- CSR build --------------------------------------------------
__global__ void k_zero_deg() {
    int i = blockIdx.x * blockDim.x + threadIdx.x;
    if (i < 3 * NAn) ((int*)g_deg)[i] = 0;
}

__global__ void __launch_bounds__(256) k_deg(const int* __restrict__ e0,
                                             const int* __restrict__ e1,
                                             const int* __restrict__ e2) {
    int idx = blockIdx.x * 256 + threadIdx.x;
    if (idx >= 3 * Ee) return;
    int r = idx / Ee;
    int e = idx - r * Ee;
    const int* edge = (r == 0) ? e0 : (r == 1) ? e1 : e2;
    int dst = __ldg(&edge[Ee + e]);
    atomicAdd(&g_deg[r][dst], 1);
}

__global__ void __launch_bounds__(1024) k_scan() {
    const int r = blockIdx.x;
    __shared__ int part[1024];
    const int t = threadIdx.x;
    const int CH = 40;  // 1024*40 >= 40000
    int base = t * CH;
    int s = 0;
#pragma unroll 4
    for (int i = 0; i < CH; i++) {
        int j = base + i;
        if (j < NAn) s += g_deg[r][j];
    }
    part[t] = s;
    __syncthreads();
    for (int d = 1; d < 1024; d <<= 1) {
        int v = (t >= d) ? part[t - d] : 0;
        __syncthreads();
        part[t] += v;
        __syncthreads();
    }
    int pre = (t == 0) ? 0 : part[t - 1];
    for (int i = 0; i < CH; i++) {
        int j = base + i;
        if (j < NAn) {
            g_off[r][j] = pre;
            g_cur[r][j] = pre;
            pre += g_deg[r][j];
        }
    }
    if (t == 1023) g_off[r][NAn] = Ee;
}

__global__ void __launch_bounds__(256) k_scatter(const int* __restrict__ e0,
                                                 const int* __restrict__ e1,
                                                 const int* __restrict__ e2) {
    int idx = blockIdx.x * 256 + threadIdx.x;
    if (idx >= 3 * Ee) return;
    int r = idx / Ee;
    int e = idx - r * Ee;
    const int* edge = (r == 0) ? e0 : (r == 1) ? e1 : e2;
    int src = __ldg(&edge[e]);
    int dst = __ldg(&edge[Ee + e]);
    int slot = atomicAdd(&g_cur[r][dst], 1);
    g_perm[r][slot] = src;
}

// ---------------- aggregation: warp per dst node, register accumulation -----
// Writes the NORMALIZED relation embedding (softmax applied). Zero if no edges.
template <int RID>  // 0 = ba (src B -> dst A), 1 = aa, 2 = ab (src A -> dst B)
__global__ void __launch_bounds__(256) k_agg() {
    const float* al = (RID == 0) ? g_al1 : (RID == 1) ? g_al2 : g_al0;
    const float* ar = (RID == 0) ? g_ar1 : (RID == 1) ? g_ar2 : g_ar0;
    const float* Hs = (RID == 0) ? g_hB : g_hA;
    float* rel = (RID == 0) ? g_rel_ba : (RID == 1) ? g_rel_aa : g_rel_ab;

    int n = (blockIdx.x * 256 + threadIdx.x) >> 5;
    if (n >= NAn) return;
    const int lane = threadIdx.x & 31;

    int beg = __ldg(&g_off[RID][n]);
    int end = __ldg(&g_off[RID][n + 1]);

    float arv = (lane < Hh) ? __ldg(&ar[n * Hh + lane]) : 0.f;
    float dsum = 0.f;
    float4 acc0 = make_float4(0.f, 0.f, 0.f, 0.f);
    float4 acc1 = make_float4(0.f, 0.f, 0.f, 0.f);

    int s = (beg < end) ? __ldg(&g_perm[RID][beg]) : 0;
    for (int i = beg; i < end; i++) {
        int s_next = (i + 1 < end) ? __ldg(&g_perm[RID][i + 1]) : 0;
        float exv = 0.f;
        if (lane < Hh) {
            exv = __expf(leaky(__ldg(&al[s * Hh + lane]) + arv));
            dsum += exv;
        }
        float ex0 = __shfl_sync(0xffffffffu, exv, lane >> 3);
        float ex1 = __shfl_sync(0xffffffffu, exv, 4 + (lane >> 3));
        const float4* hp = (const float4*)(Hs + (size_t)s * Dd);
        float4 v0 = __ldg(hp + lane);
        float4 v1 = __ldg(hp + 32 + lane);
        acc0.x += v0.x * ex0; acc0.y += v0.y * ex0;
        acc0.z += v0.z * ex0; acc0.w += v0.w * ex0;
        acc1.x += v1.x * ex1; acc1.y += v1.y * ex1;
        acc1.z += v1.z * ex1; acc1.w += v1.w * ex1;
        s = s_next;
    }

    float d0 = __shfl_sync(0xffffffffu, dsum, lane >> 3);
    float d1 = __shfl_sync(0xffffffffu, dsum, 4 + (lane >> 3));
    float i0 = d0 > 0.f ? 1.f / d0 : 0.f;
    float i1 = d1 > 0.f ? 1.f / d1 : 0.f;
    acc0.x *= i0; acc0.y *= i0; acc0.z *= i0; acc0.w *= i0;
    acc1.x *= i1; acc1.y *= i1; acc1.z *= i1; acc1.w *= i1;

    float* rp = rel + (size_t)n * Dd;
    *(float4*)(rp + lane * 4) = acc0;
    *(float4*)(rp + 128 + lane * 4) = acc1;
}

// ---------------- finalize (merged A+B): beta combine + relu ----------------
#define QR(v) v += __shfl_xor_sync(0xffffffffu, v, 1); v += __shfl_xor_sync(0xffffffffu, v, 2);

__global__ void __launch_bounds__(256) k_final(const float* __restrict__ rlA,
                                               const float* __restrict__ rrA,
                                               const float* __restrict__ rlB,
                                               const float* __restrict__ rrB,
                                               float* __restrict__ out) {
    int gw = (blockIdx.x * 256 + threadIdx.x) >> 5;
    const int lane = threadIdx.x & 31;
    const int off = lane * 8;

    if (gw < NAn) {
        int n = gw;
        size_t base = (size_t)n * Dd + off;
        float4 h0 = *(const float4*)(g_hA + base);
        float4 h1 = *(const float4*)(g_hA + base + 4);
        float4 e00 = *(const float4*)(g_rel_ba + base);
        float4 e01 = *(const float4*)(g_rel_ba + base + 4);
        float4 e10 = *(const float4*)(g_rel_aa + base);
        float4 e11 = *(const float4*)(g_rel_aa + base + 4);

        float4 rl0 = *(const float4*)(rlA + off);
        float4 rl1 = *(const float4*)(rlA + off + 4);
        float4 rr0 = *(const float4*)(rrA + off);
        float4 rr1 = *(const float4*)(rrA + off + 4);

        float bl = dot4(h0, rl0) + dot4(h1, rl1);
        float b0 = dot4(e00, rr0) + dot4(e01, rr1);
        float b1 = dot4(e10, rr0) + dot4(e11, rr1);
        float b2 = dot4(h0, rr0) + dot4(h1, rr1);
        QR(bl) QR(b0) QR(b1) QR(b2)

        float s0 = leaky(bl + b0), s1 = leaky(bl + b1), s2 = leaky(bl + b2);
        float mx = fmaxf(s0, fmaxf(s1, s2));
        float w0 = __expf(s0 - mx), w1 = __expf(s1 - mx), w2 = __expf(s2 - mx);
        float inv = 1.f / (w0 + w1 + w2);
        w0 *= inv; w1 *= inv; w2 *= inv;

        float4 o0, o1;
        o0.x = fmaxf(e00.x * w0 + e10.x * w1 + h0.x * w2, 0.f);
        o0.y = fmaxf(e00.y * w0 + e10.y * w1 + h0.y * w2, 0.f);
        o0.z = fmaxf(e00.z * w0 + e10.z * w1 + h0.z * w2, 0.f);
        o0.w = fmaxf(e00.w * w0 + e10.w * w1 + h0.w * w2, 0.f);
        o1.x = fmaxf(e01.x * w0 + e11.x * w1 + h1.x * w2, 0.f);
        o1.y = fmaxf(e01.y * w0 + e11.y * w1 + h1.y * w2, 0.f);
        o1.z = fmaxf(e01.z * w0 + e11.z * w1 + h1.z * w2, 0.f);
        o1.w = fmaxf(e01.w * w0 + e11.w * w1 + h1.w * w2, 0.f);
        *(float4*)(out + base) = o0;
        *(float4*)(out + base + 4) = o1;
    } else if (gw < NAn + NBn) {
        int n = gw - NAn;
        size_t base = (size_t)n * Dd + off;
        float4 h0 = *(const float4*)(g_hB + base);
        float4 h1 = *(const float4*)(g_hB + base + 4);
        float4 e00 = *(const float4*)(g_rel_ab + base);
        float4 e01 = *(const float4*)(g_rel_ab + base + 4);

        float4 rl0 = *(const float4*)(rlB + off);
        float4 rl1 = *(const float4*)(rlB + off + 4);
        float4 rr0 = *(const float4*)(rrB + off);
        float4 rr1 = *(const float4*)(rrB + off + 4);

        float bl = dot4(h0, rl0) + dot4(h1, rl1);
        float b0 = dot4(e00, rr0) + dot4(e01, rr1);
        float b1 = dot4(h0, rr0) + dot4(h1, rr1);
        QR(bl) QR(b0) QR(b1)

        float s0 = leaky(bl + b0), s1 = leaky(bl + b1);
        float mx = fmaxf(s0, s1);
        float w0 = __expf(s0 - mx), w1 = __expf(s1 - mx);
        float inv = 1.f / (w0 + w1);
        w0 *= inv; w1 *= inv;

        float4 o0, o1;
        o0.x = fmaxf(e00.x * w0 + h0.x * w1, 0.f);
        o0.y = fmaxf(e00.y * w0 + h0.y * w1, 0.f);
        o0.z = fmaxf(e00.z * w0 + h0.z * w1, 0.f);
        o0.w = fmaxf(e00.w * w0 + h0.w * w1, 0.f);
        o1.x = fmaxf(e01.x * w0 + h1.x * w1, 0.f);
        o1.y = fmaxf(e01.y * w0 + h1.y * w1, 0.f);
        o1.z = fmaxf(e01.z * w0 + h1.z * w1, 0.f);
        o1.w = fmaxf(e01.w * w0 + h1.w * w1, 0.f);
        size_t obase = (size_t)(NAn + n) * Dd + off;
        *(float4*)(out + obase) = o0;
        *(float4*)(out + obase + 4) = o1;
    }
}

// ---------------- launch -----------------------------------------------------
extern "C" void kernel_launch(void* const* d_in, const int* in_sizes, int n_in,
                              void* d_out, int out_size) {
    const float* xA     = (const float*)d_in[0];
    const float* xB     = (const float*)d_in[1];
    const int*   e_ab   = (const int*)d_in[2];
    const int*   e_ba   = (const int*)d_in[3];
    const int*   e_aa   = (const int*)d_in[4];
    const float* WA     = (const float*)d_in[5];
    const float* bA     = (const float*)d_in[6];
    const float* WB     = (const float*)d_in[7];
    const float* bB     = (const float*)d_in[8];
    const float* attn_l = (const float*)d_in[9];
    const float* attn_r = (const float*)d_in[10];
    const float* rlA    = (const float*)d_in[11];
    const float* rrA    = (const float*)d_in[12];
    const float* rlB    = (const float*)d_in[13];
    const float* rrB    = (const float*)d_in[14];
    float* out = (float*)d_out;

    // CSR build (depends only on edge lists)
    k_zero_deg<<<(3 * NAn + 255) / 256, 256>>>();
    k_deg<<<(3 * Ee + 255) / 256, 256>>>(e_ba, e_aa, e_ab);
    k_scan<<<3, 1024>>>();
    k_scatter<<<(3 * Ee + 255) / 256, 256>>>(e_ba, e_aa, e_ab);

    dim3 gg(2, (NAn + 127) / 128);
    k_gemm<0><<<gg, 256>>>(xA, WA, bA);
    k_gemm<1><<<gg, 256>>>(xB, WB, bB);
    k_alpha<<<((NAn + NBn) * 32 + 255) / 256, 256>>>(attn_l, attn_r);

    k_agg<0><<<(NAn * 32 + 255) / 256, 256>>>();
    k_agg<1><<<(NAn * 32 + 255) / 256, 256>>>();
    k_agg<2><<<(NBn * 32 + 255) / 256, 256>>>();

    k_final<<<((NAn + NBn) * 32 + 255) / 256, 256>>>(rlA, rrA, rlB, rrB, out);
}

// round 13
// speedup vs baseline: 1.9372x; 1.0549x over previous
#include <cuda_runtime.h>
#include <math.h>

#define NAn 40000
#define NBn 40000
#define Hh  8
#define Cc  32
#define Dd  256
#define Ee  400000

// ---------------- device scratch (module globals; no runtime allocation) ----
__device__ __align__(256) float g_hA[(size_t)NAn * Dd];
__device__ __align__(256) float g_hB[(size_t)NBn * Dd];
__device__ __align__(256) float g_rel_ba[(size_t)NAn * Dd];
__device__ __align__(256) float g_rel_aa[(size_t)NAn * Dd];
__device__ __align__(256) float g_rel_ab[(size_t)NBn * Dd];
__device__ __align__(256) float g_al0[NAn * Hh];
__device__ __align__(256) float g_ar1[NAn * Hh];
__device__ __align__(256) float g_al2[NAn * Hh];
__device__ __align__(256) float g_ar2[NAn * Hh];
__device__ __align__(256) float g_ar0[NBn * Hh];
__device__ __align__(256) float g_al1[NBn * Hh];
// CSR scratch (dst-bucketed adjacency, rebuilt every call)
__device__ int g_deg[3][NAn];
__device__ int g_off[3][NAn + 1];
__device__ int g_cur[3][NAn];
__device__ int g_perm[3][Ee];   // src node per CSR slot

// ---------------- helpers ---------------------------------------------------
__device__ __forceinline__ float leaky(float x) { return x >= 0.f ? x : 0.2f * x; }
__device__ __forceinline__ float dot4(float4 a, float4 b) {
    return a.x * b.x + a.y * b.y + a.z * b.z + a.w * b.w;
}

// ---------------- GEMM: H = X@W + b (M x 256 x 256), 128x128x16, 8x8/thread -
// Double-buffered SMEM, single __syncthreads per k-chunk. LDG prefetch into
// registers overlaps the 1024-FFMA compute block.
template <int MODE>  // 0 = A, 1 = B
__global__ void __launch_bounds__(256, 2) k_gemm(const float* __restrict__ X,
                                                 const float* __restrict__ W,
                                                 const float* __restrict__ bias) {
    __shared__ float As[2][16][128];
    __shared__ float Bs[2][16][128];
    const int tid = threadIdx.x;
    const int bn = blockIdx.x * 128;
    const int bm = blockIdx.y * 128;
    const int M = MODE ? NBn : NAn;
    const int tx8 = tid & 15;
    const int ty8 = tid >> 4;

    float acc[8][8];
#pragma unroll
    for (int i = 0; i < 8; i++)
#pragma unroll
        for (int j = 0; j < 8; j++) acc[i][j] = 0.f;

    const int arow = tid >> 1;         // 0..127
    const int akc = (tid & 1) * 8;     // 0 or 8
    const int brow = tid >> 4;         // 0..15
    const int bcol = (tid & 15) * 4;   // 0..60
    const int gr = min(bm + arow, M - 1);

    float4 a0, a1, b0, b1;
    // prologue: chunk 0 load + store to buffer 0
    a0 = *(const float4*)&X[(size_t)gr * Dd + akc];
    a1 = *(const float4*)&X[(size_t)gr * Dd + akc + 4];
    b0 = *(const float4*)&W[(size_t)brow * Dd + bn + bcol];
    b1 = *(const float4*)&W[(size_t)brow * Dd + bn + bcol + 64];
    As[0][akc + 0][arow] = a0.x; As[0][akc + 1][arow] = a0.y;
    As[0][akc + 2][arow] = a0.z; As[0][akc + 3][arow] = a0.w;
    As[0][akc + 4][arow] = a1.x; As[0][akc + 5][arow] = a1.y;
    As[0][akc + 6][arow] = a1.z; As[0][akc + 7][arow] = a1.w;
    *(float4*)&Bs[0][brow][bcol] = b0;
    *(float4*)&Bs[0][brow][bcol + 64] = b1;

    const int NC = Dd / 16;  // 16 chunks
    for (int c = 0; c < NC; c++) {
        __syncthreads();  // buffer c&1 fully written
        const int cur = c & 1;
        if (c + 1 < NC) {
            int k0 = (c + 1) * 16;
            a0 = *(const float4*)&X[(size_t)gr * Dd + k0 + akc];
            a1 = *(const float4*)&X[(size_t)gr * Dd + k0 + akc + 4];
            b0 = *(const float4*)&W[(size_t)(k0 + brow) * Dd + bn + bcol];
            b1 = *(const float4*)&W[(size_t)(k0 + brow) * Dd + bn + bcol + 64];
        }
#pragma unroll
        for (int k = 0; k < 16; k++) {
            float a[8], b[8];
            *(float4*)&a[0] = *(float4*)&As[cur][k][ty8 * 4];
            *(float4*)&a[4] = *(float4*)&As[cur][k][64 + ty8 * 4];
            *(float4*)&b[0] = *(float4*)&Bs[cur][k][tx8 * 4];
            *(float4*)&b[4] = *(float4*)&Bs[cur][k][64 + tx8 * 4];
#pragma unroll
            for (int i = 0; i < 8; i++)
#pragma unroll
                for (int j = 0; j < 8; j++) acc[i][j] += a[i] * b[j];
        }
        if (c + 1 < NC) {
            const int nxt = (c + 1) & 1;  // buffer last read in chunk c-1: safe
            As[nxt][akc + 0][arow] = a0.x; As[nxt][akc + 1][arow] = a0.y;
            As[nxt][akc + 2][arow] = a0.z; As[nxt][akc + 3][arow] = a0.w;
            As[nxt][akc + 4][arow] = a1.x; As[nxt][akc + 5][arow] = a1.y;
            As[nxt][akc + 6][arow] = a1.z; As[nxt][akc + 7][arow] = a1.w;
            *(float4*)&Bs[nxt][brow][bcol] = b0;
            *(float4*)&Bs[nxt][brow][bcol + 64] = b1;
        }
    }

    float* Hout = MODE ? g_hB : g_hA;
    float4 bb0 = *(const float4*)&bias[bn + tx8 * 4];
    float4 bb1 = *(const float4*)&bias[bn + 64 + tx8 * 4];

#pragma unroll
    for (int i = 0; i < 8; i++) {
        int row = bm + ((i < 4) ? (ty8 * 4 + i) : (64 + ty8 * 4 + i - 4));
        if (row >= M) continue;
        size_t base = (size_t)row * Dd + bn;
        float4 o0 = make_float4(acc[i][0] + bb0.x, acc[i][1] + bb0.y,
                                acc[i][2] + bb0.z, acc[i][3] + bb0.w);
        float4 o1 = make_float4(acc[i][4] + bb1.x, acc[i][5] + bb1.y,
                                acc[i][6] + bb1.z, acc[i][7] + bb1.w);
        *(float4*)&Hout[base + tx8 * 4] = o0;
        *(float4*)&Hout[base + tx8 * 4 + 64] = o1;
    }
}

// ---------------- alphas: warp per node, coalesced --------------------------
__global__ void __launch_bounds__(256) k_alpha(const float* __restrict__ attn_l,
                                               const float* __restrict__ attn_r) {
    int gw = (blockIdx.x * 256 + threadIdx.x) >> 5;
    const int lane = threadIdx.x & 31;
    const int off = lane * 8;
    const int h = lane >> 2;
    const bool wr = (lane & 3) == 0;
#define R2(v) v += __shfl_xor_sync(0xffffffffu, v, 1); v += __shfl_xor_sync(0xffffffffu, v, 2);

    if (gw < NAn) {
        int n = gw;
        size_t base = (size_t)n * Dd + off;
        float4 v0 = *(const float4*)(g_hA + base);
        float4 v1 = *(const float4*)(g_hA + base + 4);
        float d0 = dot4(v0, __ldg((const float4*)(attn_l + off)))
                 + dot4(v1, __ldg((const float4*)(attn_l + off + 4)));
        float d1 = dot4(v0, __ldg((const float4*)(attn_r + 256 + off)))
                 + dot4(v1, __ldg((const float4*)(attn_r + 256 + off + 4)));
        float d2 = dot4(v0, __ldg((const float4*)(attn_l + 512 + off)))
                 + dot4(v1, __ldg((const float4*)(attn_l + 512 + off + 4)));
        float d3 = dot4(v0, __ldg((const float4*)(attn_r + 512 + off)))
                 + dot4(v1, __ldg((const float4*)(attn_r + 512 + off + 4)));
        R2(d0) R2(d1) R2(d2) R2(d3)
        if (wr) {
            g_al0[n * Hh + h] = d0;
            g_ar1[n * Hh + h] = d1;
            g_al2[n * Hh + h] = d2;
            g_ar2[n * Hh + h] = d3;
        }
    } else if (gw < NAn + NBn) {
        int n = gw - NAn;
        size_t base = (size_t)n * Dd + off;
        float4 v0 = *(const float4*)(g_hB + base);
        float4 v1 = *(const float4*)(g_hB + base + 4);
        float d0 = dot4(v0, __ldg((const float4*)(attn_r + off)))
                 + dot4(v1, __ldg((const float4*)(attn_r + off + 4)));
        float d1 = dot4(v0, __ldg((const float4*)(attn_l + 256 + off)))
                 + dot4(v1, __ldg((const float4*)(attn_l + 256 + off + 4)));
        R2(d0) R2(d1)
        if (wr) {
            g_ar0[n * Hh + h] = d0;
            g_al1[n * Hh + h] = d1;
        }
    }
}

// ---------------- CSR build --------------------------------------------------
__global__ void k_zero_deg() {
    int i = blockIdx.x * blockDim.x + threadIdx.x;
    if (i < 3 * NAn) ((int*)g_deg)[i] = 0;
}

__global__ void __launch_bounds__(256) k_deg(const int* __restrict__ e0,
                                             const int* __restrict__ e1,
                                             const int* __restrict__ e2) {
    int idx = blockIdx.x * 256 + threadIdx.x;
    if (idx >= 3 * Ee) return;
    int r = idx / Ee;
    int e = idx - r * Ee;
    const int* edge = (r == 0) ? e0 : (r == 1) ? e1 : e2;
    int dst = __ldg(&edge[Ee + e]);
    atomicAdd(&g_deg[r][dst], 1);
}

__global__ void __launch_bounds__(1024) k_scan() {
    const int r = blockIdx.x;
    __shared__ int part[1024];
    const int t = threadIdx.x;
    const int CH = 40;  // 1024*40 >= 40000
    int base = t * CH;
    int s = 0;
#pragma unroll 4
    for (int i = 0; i < CH; i++) {
        int j = base + i;
        if (j < NAn) s += g_deg[r][j];
    }
    part[t] = s;
    __syncthreads();
    for (int d = 1; d < 1024; d <<= 1) {
        int v = (t >= d) ? part[t - d] : 0;
        __syncthreads();
        part[t] += v;
        __syncthreads();
    }
    int pre = (t == 0) ? 0 : part[t - 1];
    for (int i = 0; i < CH; i++) {
        int j = base + i;
        if (j < NAn) {
            g_off[r][j] = pre;
            g_cur[r][j] = pre;
            pre += g_deg[r][j];
        }
    }
    if (t == 1023) g_off[r][NAn] = Ee;
}

__global__ void __launch_bounds__(256) k_scatter(const int* __restrict__ e0,
                                                 const int* __restrict__ e1,
                                                 const int* __restrict__ e2) {
    int idx = blockIdx.x * 256 + threadIdx.x;
    if (idx >= 3 * Ee) return;
    int r = idx / Ee;
    int e = idx - r * Ee;
    const int* edge = (r == 0) ? e0 : (r == 1) ? e1 : e2;
    int src = __ldg(&edge[e]);
    int dst = __ldg(&edge[Ee + e]);
    int slot = atomicAdd(&g_cur[r][dst], 1);
    g_perm[r][slot] = src;
}

// ---------------- aggregation: warp per dst node, 2-edge unrolled -----------
// Writes the NORMALIZED relation embedding (softmax applied). Zero if no edges.
template <int RID>  // 0 = ba (src B -> dst A), 1 = aa, 2 = ab (src A -> dst B)
__global__ void __launch_bounds__(256) k_agg() {
    const float* al = (RID == 0) ? g_al1 : (RID == 1) ? g_al2 : g_al0;
    const float* ar = (RID == 0) ? g_ar1 : (RID == 1) ? g_ar2 : g_ar0;
    const float* Hs = (RID == 0) ? g_hB : g_hA;
    float* rel = (RID == 0) ? g_rel_ba : (RID == 1) ? g_rel_aa : g_rel_ab;

    int n = (blockIdx.x * 256 + threadIdx.x) >> 5;
    if (n >= NAn) return;
    const int lane = threadIdx.x & 31;

    int beg = __ldg(&g_off[RID][n]);
    int end = __ldg(&g_off[RID][n + 1]);

    float arv = (lane < Hh) ? __ldg(&ar[n * Hh + lane]) : 0.f;
    float dsum = 0.f;
    float4 acc0 = make_float4(0.f, 0.f, 0.f, 0.f);
    float4 acc1 = make_float4(0.f, 0.f, 0.f, 0.f);

    const int b0i = lane >> 3;       // broadcast lane for heads 0..3
    const int b1i = 4 + (lane >> 3); // broadcast lane for heads 4..7

    int i = beg;
    // ---- 2-edge unrolled mainloop: batch gathers for MLP ----
    for (; i + 1 < end; i += 2) {
        int sa = __ldg(&g_perm[RID][i]);
        int sb = __ldg(&g_perm[RID][i + 1]);
        float ea = 0.f, eb = 0.f;
        if (lane < Hh) {
            float la = __ldg(&al[sa * Hh + lane]);
            float lb = __ldg(&al[sb * Hh + lane]);
            ea = __expf(leaky(la + arv));
            eb = __expf(leaky(lb + arv));
            dsum += ea + eb;
        }
        const float4* pa = (const float4*)(Hs + (size_t)sa * Dd);
        const float4* pb = (const float4*)(Hs + (size_t)sb * Dd);
        float4 va0 = __ldg(pa + lane);
        float4 va1 = __ldg(pa + 32 + lane);
        float4 vb0 = __ldg(pb + lane);
        float4 vb1 = __ldg(pb + 32 + lane);
        float ea0 = __shfl_sync(0xffffffffu, ea, b0i);
        float ea1 = __shfl_sync(0xffffffffu, ea, b1i);
        float eb0 = __shfl_sync(0xffffffffu, eb, b0i);
        float eb1 = __shfl_sync(0xffffffffu, eb, b1i);
        acc0.x += va0.x * ea0 + vb0.x * eb0;
        acc0.y += va0.y * ea0 + vb0.y * eb0;
        acc0.z += va0.z * ea0 + vb0.z * eb0;
        acc0.w += va0.w * ea0 + vb0.w * eb0;
        acc1.x += va1.x * ea1 + vb1.x * eb1;
        acc1.y += va1.y * ea1 + vb1.y * eb1;
        acc1.z += va1.z * ea1 + vb1.z * eb1;
        acc1.w += va1.w * ea1 + vb1.w * eb1;
    }
    // ---- tail edge ----
    if (i < end) {
        int s = __ldg(&g_perm[RID][i]);
        float exv = 0.f;
        if (lane < Hh) {
            exv = __expf(leaky(__ldg(&al[s * Hh + lane]) + arv));
            dsum += exv;
        }
        float ex0 = __shfl_sync(0xffffffffu, exv, b0i);
        float ex1 = __shfl_sync(0xffffffffu, exv, b1i);
        const float4* hp = (const float4*)(Hs + (size_t)s * Dd);
        float4 v0 = __ldg(hp + lane);
        float4 v1 = __ldg(hp + 32 + lane);
        acc0.x += v0.x * ex0; acc0.y += v0.y * ex0;
        acc0.z += v0.z * ex0; acc0.w += v0.w * ex0;
        acc1.x += v1.x * ex1; acc1.y += v1.y * ex1;
        acc1.z += v1.z * ex1; acc1.w += v1.w * ex1;
    }

    float d0 = __shfl_sync(0xffffffffu, dsum, b0i);
    float d1 = __shfl_sync(0xffffffffu, dsum, b1i);
    float i0 = d0 > 0.f ? 1.f / d0 : 0.f;
    float i1 = d1 > 0.f ? 1.f / d1 : 0.f;
    acc0.x *= i0; acc0.y *= i0; acc0.z *= i0; acc0.w *= i0;
    acc1.x *= i1; acc1.y *= i1; acc1.z *= i1; acc1.w *= i1;

    float* rp = rel + (size_t)n * Dd;
    *(float4*)(rp + lane * 4) = acc0;
    *(float4*)(rp + 128 + lane * 4) = acc1;
}

// ---------------- finalize (merged A+B): beta combine + relu ----------------
#define QR(v) v += __shfl_xor_sync(0xffffffffu, v, 1); v += __shfl_xor_sync(0xffffffffu, v, 2);

__global__ void __launch_bounds__(256) k_final(const float* __restrict__ rlA,
                                               const float* __restrict__ rrA,
                                               const float* __restrict__ rlB,
                                               const float* __restrict__ rrB,
                                               float* __restrict__ out) {
    int gw = (blockIdx.x * 256 + threadIdx.x) >> 5;
    const int lane = threadIdx.x & 31;
    const int off = lane * 8;

    if (gw < NAn) {
        int n = gw;
        size_t base = (size_t)n * Dd + off;
        float4 h0 = *(const float4*)(g_hA + base);
        float4 h1 = *(const float4*)(g_hA + base + 4);
        float4 e00 = *(const float4*)(g_rel_ba + base);
        float4 e01 = *(const float4*)(g_rel_ba + base + 4);
        float4 e10 = *(const float4*)(g_rel_aa + base);
        float4 e11 = *(const float4*)(g_rel_aa + base + 4);

        float4 rl0 = *(const float4*)(rlA + off);
        float4 rl1 = *(const float4*)(rlA + off + 4);
        float4 rr0 = *(const float4*)(rrA + off);
        float4 rr1 = *(const float4*)(rrA + off + 4);

        float bl = dot4(h0, rl0) + dot4(h1, rl1);
        float b0 = dot4(e00, rr0) + dot4(e01, rr1);
        float b1 = dot4(e10, rr0) + dot4(e11, rr1);
        float b2 = dot4(h0, rr0) + dot4(h1, rr1);
        QR(bl) QR(b0) QR(b1) QR(b2)

        float s0 = leaky(bl + b0), s1 = leaky(bl + b1), s2 = leaky(bl + b2);
        float mx = fmaxf(s0, fmaxf(s1, s2));
        float w0 = __expf(s0 - mx), w1 = __expf(s1 - mx), w2 = __expf(s2 - mx);
        float inv = 1.f / (w0 + w1 + w2);
        w0 *= inv; w1 *= inv; w2 *= inv;

        float4 o0, o1;
        o0.x = fmaxf(e00.x * w0 + e10.x * w1 + h0.x * w2, 0.f);
        o0.y = fmaxf(e00.y * w0 + e10.y * w1 + h0.y * w2, 0.f);
        o0.z = fmaxf(e00.z * w0 + e10.z * w1 + h0.z * w2, 0.f);
        o0.w = fmaxf(e00.w * w0 + e10.w * w1 + h0.w * w2, 0.f);
        o1.x = fmaxf(e01.x * w0 + e11.x * w1 + h1.x * w2, 0.f);
        o1.y = fmaxf(e01.y * w0 + e11.y * w1 + h1.y * w2, 0.f);
        o1.z = fmaxf(e01.z * w0 + e11.z * w1 + h1.z * w2, 0.f);
        o1.w = fmaxf(e01.w * w0 + e11.w * w1 + h1.w * w2, 0.f);
        *(float4*)(out + base) = o0;
        *(float4*)(out + base + 4) = o1;
    } else if (gw < NAn + NBn) {
        int n = gw - NAn;
        size_t base = (size_t)n * Dd + off;
        float4 h0 = *(const float4*)(g_hB + base);
        float4 h1 = *(const float4*)(g_hB + base + 4);
        float4 e00 = *(const float4*)(g_rel_ab + base);
        float4 e01 = *(const float4*)(g_rel_ab + base + 4);

        float4 rl0 = *(const float4*)(rlB + off);
        float4 rl1 = *(const float4*)(rlB + off + 4);
        float4 rr0 = *(const float4*)(rrB + off);
        float4 rr1 = *(const float4*)(rrB + off + 4);

        float bl = dot4(h0, rl0) + dot4(h1, rl1);
        float b0 = dot4(e00, rr0) + dot4(e01, rr1);
        float b1 = dot4(h0, rr0) + dot4(h1, rr1);
        QR(bl) QR(b0) QR(b1)

        float s0 = leaky(bl + b0), s1 = leaky(bl + b1);
        float mx = fmaxf(s0, s1);
        float w0 = __expf(s0 - mx), w1 = __expf(s1 - mx);
        float inv = 1.f / (w0 + w1);
        w0 *= inv; w1 *= inv;

        float4 o0, o1;
        o0.x = fmaxf(e00.x * w0 + h0.x * w1, 0.f);
        o0.y = fmaxf(e00.y * w0 + h0.y * w1, 0.f);
        o0.z = fmaxf(e00.z * w0 + h0.z * w1, 0.f);
        o0.w = fmaxf(e00.w * w0 + h0.w * w1, 0.f);
        o1.x = fmaxf(e01.x * w0 + h1.x * w1, 0.f);
        o1.y = fmaxf(e01.y * w0 + h1.y * w1, 0.f);
        o1.z = fmaxf(e01.z * w0 + h1.z * w1, 0.f);
        o1.w = fmaxf(e01.w * w0 + h1.w * w1, 0.f);
        size_t obase = (size_t)(NAn + n) * Dd + off;
        *(float4*)(out + obase) = o0;
        *(float4*)(out + obase + 4) = o1;
    }
}

// ---------------- launch -----------------------------------------------------
extern "C" void kernel_launch(void* const* d_in, const int* in_sizes, int n_in,
                              void* d_out, int out_size) {
    const float* xA     = (const float*)d_in[0];
    const float* xB     = (const float*)d_in[1];
    const int*   e_ab   = (const int*)d_in[2];
    const int*   e_ba   = (const int*)d_in[3];
    const int*   e_aa   = (const int*)d_in[4];
    const float* WA     = (const float*)d_in[5];
    const float* bA     = (const float*)d_in[6];
    const float* WB     = (const float*)d_in[7];
    const float* bB     = (const float*)d_in[8];
    const float* attn_l = (const float*)d_in[9];
    const float* attn_r = (const float*)d_in[10];
    const float* rlA    = (const float*)d_in[11];
    const float* rrA    = (const float*)d_in[12];
    const float* rlB    = (const float*)d_in[13];
    const float* rrB    = (const float*)d_in[14];
    float* out = (float*)d_out;

    // CSR build (depends only on edge lists)
    k_zero_deg<<<(3 * NAn + 255) / 256, 256>>>();
    k_deg<<<(3 * Ee + 255) / 256, 256>>>(e_ba, e_aa, e_ab);
    k_scan<<<3, 1024>>>();
    k_scatter<<<(3 * Ee + 255) / 256, 256>>>(e_ba, e_aa, e_ab);

    dim3 gg(2, (NAn + 127) / 128);
    k_gemm<0><<<gg, 256>>>(xA, WA, bA);
    k_gemm<1><<<gg, 256>>>(xB, WB, bB);
    k_alpha<<<((NAn + NBn) * 32 + 255) / 256, 256>>>(attn_l, attn_r);

    k_agg<0><<<(NAn * 32 + 255) / 256, 256>>>();
    k_agg<1><<<(NAn * 32 + 255) / 256, 256>>>();
    k_agg<2><<<(NBn * 32 + 255) / 256, 256>>>();

    k_final<<<((NAn + NBn) * 32 + 255) / 256, 256>>>(rlA, rrA, rlB, rrB, out);
}